// round 2
// baseline (speedup 1.0000x reference)
#include <cuda_runtime.h>
#include <math.h>

// ---------------- problem constants ----------------
#define BATCH 4
#define NY    16384
#define NX    4096
#define CY    128
#define CX    256
#define DIM   384        // CY + CX
#define C1    512
#define C2    256
#define C3    128
#define MROWS 65536      // BATCH * NY
#define SB    64         // stats partial blocks

// ---------------- scratch (static device allocations only) ----------------
__device__ float g_F [(size_t)MROWS * DIM];   // concat features  [M, 384]
__device__ float g_T1[(size_t)MROWS * C1];    // layer1 raw       [M, 512]
__device__ float g_T2[(size_t)MROWS * C2];    // layer2 raw       [M, 256]
__device__ float g_T3[(size_t)MROWS * C3];    // layer3 raw       [M, 128]
__device__ int   g_idx[MROWS * 3];
__device__ float g_w  [MROWS * 3];
__device__ float g_ps [C1 * SB];              // partial sums   (max channels = 512)
__device__ float g_pq [C1 * SB];              // partial sumsq
__device__ float g_sc1[C1], g_sh1[C1];
__device__ float g_sc2[C2], g_sh2[C2];
__device__ float g_sc3[C3], g_sh3[C3];

__device__ __forceinline__ float to_tf32(float x) {
    float r;
    asm("cvt.rna.tf32.f32 %0, %1;" : "=f"(r) : "f"(x));
    return r;
}

// ---------------- KNN (K=3), reference-matching arithmetic ----------------
// d = (yy + xx) - 2*dot, all in exact fp32 rn ops (no FMA contraction),
// matching jnp: sum(y*y) + sum(x*x) - 2*einsum(y,x)
__global__ __launch_bounds__(128) void knn_kernel(
    const float* __restrict__ y_points, const float* __restrict__ x_points,
    int* __restrict__ out_idx, float* __restrict__ out_w)
{
    __shared__ float xp[NX * 3];   // 48 KB
    __shared__ float xs[NX];       // 16 KB : |x|^2
    const int m0 = blockIdx.x * 128;
    const int b  = m0 / NY;
    const float* xb = x_points + (size_t)b * NX * 3;
    for (int i = threadIdx.x; i < NX * 3; i += 128) xp[i] = xb[i];
    __syncthreads();
    for (int j = threadIdx.x; j < NX; j += 128) {
        const float x0 = xp[3 * j + 0], x1 = xp[3 * j + 1], x2 = xp[3 * j + 2];
        xs[j] = __fadd_rn(__fadd_rn(__fmul_rn(x0, x0), __fmul_rn(x1, x1)), __fmul_rn(x2, x2));
    }
    __syncthreads();

    const int m = m0 + threadIdx.x;
    const float py0 = y_points[(size_t)m * 3 + 0];
    const float py1 = y_points[(size_t)m * 3 + 1];
    const float py2 = y_points[(size_t)m * 3 + 2];
    const float yy = __fadd_rn(__fadd_rn(__fmul_rn(py0, py0), __fmul_rn(py1, py1)), __fmul_rn(py2, py2));

    float d0 = 3.4e38f, d1 = 3.4e38f, d2 = 3.4e38f;
    int   i0 = 0, i1 = 0, i2 = 0;

    for (int j = 0; j < NX; j++) {
        const float x0 = xp[3 * j + 0], x1 = xp[3 * j + 1], x2 = xp[3 * j + 2];
        const float dot = __fadd_rn(__fadd_rn(__fmul_rn(py0, x0), __fmul_rn(py1, x1)), __fmul_rn(py2, x2));
        const float d = __fsub_rn(__fadd_rn(yy, xs[j]), __fmul_rn(2.0f, dot));
        if (d < d2) {
            if (d < d1) {
                d2 = d1; i2 = i1;
                if (d < d0) { d1 = d0; i1 = i0; d0 = d; i0 = j; }
                else        { d1 = d;  i1 = j; }
            } else { d2 = d; i2 = j; }
        }
    }

    // reference: w = 1/(d+eps); w = w / sum(w)   (true divisions)
    const float w0 = __fdiv_rn(1.0f, __fadd_rn(d0, 1e-8f));
    const float w1 = __fdiv_rn(1.0f, __fadd_rn(d1, 1e-8f));
    const float w2 = __fdiv_rn(1.0f, __fadd_rn(d2, 1e-8f));
    const float s  = __fadd_rn(__fadd_rn(w0, w1), w2);
    out_idx[m * 3 + 0] = i0; out_idx[m * 3 + 1] = i1; out_idx[m * 3 + 2] = i2;
    out_w[m * 3 + 0] = __fdiv_rn(w0, s);
    out_w[m * 3 + 1] = __fdiv_rn(w1, s);
    out_w[m * 3 + 2] = __fdiv_rn(w2, s);
}

// ---------------- gather + concat -> F [M, 384] ----------------
__global__ __launch_bounds__(DIM) void gather_kernel(
    const float* __restrict__ y_feats, const float* __restrict__ x_feats,
    const int* __restrict__ idx, const float* __restrict__ w,
    float* __restrict__ F)
{
    const int m = blockIdx.x;
    const int c = threadIdx.x;
    if (c < CY) {
        F[(size_t)m * DIM + c] = y_feats[(size_t)m * CY + c];
    } else {
        const int b  = m / NY;
        const int cc = c - CY;
        const float* xb = x_feats + (size_t)b * NX * CX;
        const int i0 = idx[m * 3 + 0], i1 = idx[m * 3 + 1], i2 = idx[m * 3 + 2];
        const float w0 = w[m * 3 + 0], w1 = w[m * 3 + 1], w2 = w[m * 3 + 2];
        // reference: sum(nb*w, axis=2) -> ((w0*f0 + w1*f1) + w2*f2), exact rn ops
        const float f0 = __fmul_rn(w0, xb[(size_t)i0 * CX + cc]);
        const float f1 = __fmul_rn(w1, xb[(size_t)i1 * CX + cc]);
        const float f2 = __fmul_rn(w2, xb[(size_t)i2 * CX + cc]);
        F[(size_t)m * DIM + c] = __fadd_rn(__fadd_rn(f0, f1), f2);
    }
}

// ---------------- SIMT TF32-emulating GEMM: C[M,N] = act(A)[M,K] * W[N,K]^T + bias ----
// A and W values are rounded to TF32 (cvt.rna.tf32) before accumulation, matching
// XLA/cuBLAS TF32 matmul numerics (products of tf32 inputs are exact in fp32).
// act(A) optionally applies previous layer's BN+ReLU on load (FUSE).
template<int KDIM, int NDIM, bool FUSE>
__global__ __launch_bounds__(256) void gemm_kernel(
    const float* __restrict__ A, const float* __restrict__ W,
    const float* __restrict__ bias,
    const float* __restrict__ sc, const float* __restrict__ sh,
    float* __restrict__ C)
{
    __shared__ float As[8][128];
    __shared__ float Bs[8][128];

    const int m0 = blockIdx.x * 128;
    const int n0 = blockIdx.y * 128;
    const int tid  = threadIdx.x;
    const int tx   = tid & 15;        // 16 cols of 8
    const int ty   = tid >> 4;        // 16 rows of 8
    const int lrow = tid >> 1;        // 0..127
    const int lcol = (tid & 1) * 4;   // 0 or 4

    const float* Aptr = A + (size_t)(m0 + lrow) * KDIM + lcol;
    const float* Wptr = W + (size_t)(n0 + lrow) * KDIM + lcol;

    float acc[8][8];
    #pragma unroll
    for (int i = 0; i < 8; i++)
        #pragma unroll
        for (int j = 0; j < 8; j++) acc[i][j] = 0.0f;

    for (int kt = 0; kt < KDIM; kt += 8) {
        float4 av = *(const float4*)(Aptr + kt);
        if constexpr (FUSE) {
            const int k = kt + lcol;
            av.x = fmaxf(av.x * sc[k + 0] + sh[k + 0], 0.0f);
            av.y = fmaxf(av.y * sc[k + 1] + sh[k + 1], 0.0f);
            av.z = fmaxf(av.z * sc[k + 2] + sh[k + 2], 0.0f);
            av.w = fmaxf(av.w * sc[k + 3] + sh[k + 3], 0.0f);
        }
        float4 bv = *(const float4*)(Wptr + kt);

        As[lcol + 0][lrow] = to_tf32(av.x); As[lcol + 1][lrow] = to_tf32(av.y);
        As[lcol + 2][lrow] = to_tf32(av.z); As[lcol + 3][lrow] = to_tf32(av.w);
        Bs[lcol + 0][lrow] = to_tf32(bv.x); Bs[lcol + 1][lrow] = to_tf32(bv.y);
        Bs[lcol + 2][lrow] = to_tf32(bv.z); Bs[lcol + 3][lrow] = to_tf32(bv.w);
        __syncthreads();

        #pragma unroll
        for (int k = 0; k < 8; k++) {
            const float4* ap = (const float4*)&As[k][ty * 8];
            const float4* bp = (const float4*)&Bs[k][tx * 8];
            float4 a0 = ap[0], a1 = ap[1];
            float4 b0 = bp[0], b1 = bp[1];
            float ar[8] = {a0.x, a0.y, a0.z, a0.w, a1.x, a1.y, a1.z, a1.w};
            float br[8] = {b0.x, b0.y, b0.z, b0.w, b1.x, b1.y, b1.z, b1.w};
            #pragma unroll
            for (int i = 0; i < 8; i++)
                #pragma unroll
                for (int j = 0; j < 8; j++)
                    acc[i][j] += ar[i] * br[j];
        }
        __syncthreads();
    }

    float bcol[8];
    #pragma unroll
    for (int j = 0; j < 8; j++) bcol[j] = bias[n0 + tx * 8 + j];

    #pragma unroll
    for (int i = 0; i < 8; i++) {
        const int m = m0 + ty * 8 + i;
        float4 o0, o1;
        o0.x = acc[i][0] + bcol[0]; o0.y = acc[i][1] + bcol[1];
        o0.z = acc[i][2] + bcol[2]; o0.w = acc[i][3] + bcol[3];
        o1.x = acc[i][4] + bcol[4]; o1.y = acc[i][5] + bcol[5];
        o1.z = acc[i][6] + bcol[6]; o1.w = acc[i][7] + bcol[7];
        float* cp = C + (size_t)m * NDIM + n0 + tx * 8;
        *(float4*)(cp)     = o0;
        *(float4*)(cp + 4) = o1;
    }
}

// ---------------- batch-norm statistics (deterministic two-phase) ----------------
template<int NDIM>
__global__ __launch_bounds__(128) void stats_kernel(
    const float* __restrict__ T, float* __restrict__ ps, float* __restrict__ pq)
{
    const int n  = blockIdx.x * 128 + threadIdx.x;
    const int mb = blockIdx.y;
    const int rows = MROWS / SB;     // 1024
    float s = 0.0f, q = 0.0f;
    const float* p = T + (size_t)mb * rows * NDIM + n;
    for (int m = 0; m < rows; m++) {
        float v = p[(size_t)m * NDIM];
        s += v; q += v * v;
    }
    ps[n * SB + mb] = s;
    pq[n * SB + mb] = q;
}

__global__ void finalize_kernel(
    const float* __restrict__ ps, const float* __restrict__ pq,
    const float* __restrict__ g, const float* __restrict__ be,
    float* __restrict__ sc, float* __restrict__ sh, int N)
{
    const int n = blockIdx.x * blockDim.x + threadIdx.x;
    if (n >= N) return;
    float s = 0.0f, q = 0.0f;
    for (int i = 0; i < SB; i++) { s += ps[n * SB + i]; q += pq[n * SB + i]; }
    const float mean = s * (1.0f / (float)MROWS);
    const float var  = q * (1.0f / (float)MROWS) - mean * mean;
    const float rstd = rsqrtf(var + 1e-5f);
    const float scale = g[n] * rstd;
    sc[n] = scale;
    sh[n] = be[n] - mean * scale;
}

// ---------------- final BN+ReLU + transpose to [B, C3, NY] ----------------
__global__ __launch_bounds__(256) void output_kernel(
    const float* __restrict__ T3, const float* __restrict__ sc,
    const float* __restrict__ sh, float* __restrict__ out)
{
    __shared__ float tile[32][33];
    const int mt = blockIdx.x * 32;
    const int ct = blockIdx.y * 32;
    const int tx = threadIdx.x;      // 32
    const int ty = threadIdx.y;      // 8
    #pragma unroll
    for (int i = ty; i < 32; i += 8) {
        const int c = ct + tx;
        float v = T3[(size_t)(mt + i) * C3 + c];
        tile[i][tx] = fmaxf(v * sc[c] + sh[c], 0.0f);
    }
    __syncthreads();
    const int m  = mt + tx;
    const int b  = m / NY;
    const int ny = m % NY;
    #pragma unroll
    for (int j = ty; j < 32; j += 8) {
        const int c = ct + j;
        out[((size_t)b * C3 + c) * NY + ny] = tile[tx][j];
    }
}

// ---------------- launch ----------------
static void* sym_addr(const void* sym) { void* p = nullptr; cudaGetSymbolAddress(&p, sym); return p; }

extern "C" void kernel_launch(void* const* d_in, const int* in_sizes, int n_in,
                              void* d_out, int out_size)
{
    const float* y_points = (const float*)d_in[0];
    const float* y_feats  = (const float*)d_in[1];
    const float* x_points = (const float*)d_in[2];
    const float* x_feats  = (const float*)d_in[3];
    const float* W1 = (const float*)d_in[4];
    const float* b1 = (const float*)d_in[5];
    const float* g1 = (const float*)d_in[6];
    const float* be1= (const float*)d_in[7];
    const float* W2 = (const float*)d_in[8];
    const float* b2 = (const float*)d_in[9];
    const float* g2 = (const float*)d_in[10];
    const float* be2= (const float*)d_in[11];
    const float* W3 = (const float*)d_in[12];
    const float* b3 = (const float*)d_in[13];
    const float* g3 = (const float*)d_in[14];
    const float* be3= (const float*)d_in[15];
    float* out = (float*)d_out;

    float* pF  = (float*)sym_addr(g_F);
    float* pT1 = (float*)sym_addr(g_T1);
    float* pT2 = (float*)sym_addr(g_T2);
    float* pT3 = (float*)sym_addr(g_T3);
    int*   pIdx= (int*)  sym_addr(g_idx);
    float* pW  = (float*)sym_addr(g_w);
    float* pPs = (float*)sym_addr(g_ps);
    float* pPq = (float*)sym_addr(g_pq);
    float* pSc1= (float*)sym_addr(g_sc1);
    float* pSh1= (float*)sym_addr(g_sh1);
    float* pSc2= (float*)sym_addr(g_sc2);
    float* pSh2= (float*)sym_addr(g_sh2);
    float* pSc3= (float*)sym_addr(g_sc3);
    float* pSh3= (float*)sym_addr(g_sh3);

    // 1) KNN + weights
    knn_kernel<<<MROWS / 128, 128>>>(y_points, x_points, pIdx, pW);
    // 2) interpolate + concat
    gather_kernel<<<MROWS, DIM>>>(y_feats, x_feats, pIdx, pW, pF);
    // 3) layer 1
    gemm_kernel<DIM, C1, false><<<dim3(MROWS / 128, C1 / 128), 256>>>(pF, W1, b1, nullptr, nullptr, pT1);
    stats_kernel<C1><<<dim3(C1 / 128, SB), 128>>>(pT1, pPs, pPq);
    finalize_kernel<<<1, C1>>>(pPs, pPq, g1, be1, pSc1, pSh1, C1);
    // 4) layer 2 (BN1+ReLU fused into A-load)
    gemm_kernel<C1, C2, true><<<dim3(MROWS / 128, C2 / 128), 256>>>(pT1, W2, b2, pSc1, pSh1, pT2);
    stats_kernel<C2><<<dim3(C2 / 128, SB), 128>>>(pT2, pPs, pPq);
    finalize_kernel<<<1, C2>>>(pPs, pPq, g2, be2, pSc2, pSh2, C2);
    // 5) layer 3 (BN2+ReLU fused into A-load)
    gemm_kernel<C2, C3, true><<<dim3(MROWS / 128, C3 / 128), 256>>>(pT2, W3, b3, pSc2, pSh2, pT3);
    stats_kernel<C3><<<dim3(C3 / 128, SB), 128>>>(pT3, pPs, pPq);
    finalize_kernel<<<1, C3>>>(pPs, pPq, g3, be3, pSc3, pSh3, C3);
    // 6) BN3+ReLU + transpose into [B, C3, NY]
    output_kernel<<<dim3(MROWS / 32, C3 / 32), dim3(32, 8)>>>(pT3, pSc3, pSh3, out);
}

// round 4
// speedup vs baseline: 1.3211x; 1.3211x over previous
#include <cuda_runtime.h>
#include <cuda_bf16.h>
#include <math.h>
#include <stdint.h>

// ---------------- problem constants ----------------
#define BATCH 4
#define NY    16384
#define NX    4096
#define CY    128
#define CX    256
#define DIM   384        // CY + CX
#define C1    512
#define C2    256
#define C3    128
#define MROWS 65536      // BATCH * NY
#define GRIDM 512        // MROWS / 128

// ---------------- scratch (static device allocations only) ----------------
__device__ __align__(256) float g_F [(size_t)MROWS * DIM];
__device__ __align__(256) float g_T1[(size_t)MROWS * C1];
__device__ __align__(256) float g_T2[(size_t)MROWS * C2];
__device__ __align__(256) float g_T3[(size_t)MROWS * C3];
__device__ __align__(256) int   g_idx[MROWS * 3];
__device__ __align__(256) float g_w  [MROWS * 3];
__device__ __align__(256) float g_ps [C1 * GRIDM];
__device__ __align__(256) float g_pq [C1 * GRIDM];
__device__ __align__(256) float g_sc1[C1], g_sh1[C1];
__device__ __align__(256) float g_sc2[C2], g_sh2[C2];
__device__ __align__(256) float g_sc3[C3], g_sh3[C3];
__device__ __align__(256) __nv_bfloat16 g_W1h[C1 * DIM], g_W1l[C1 * DIM];
__device__ __align__(256) __nv_bfloat16 g_W2h[C2 * C1],  g_W2l[C2 * C1];
__device__ __align__(256) __nv_bfloat16 g_W3h[C3 * C2],  g_W3l[C3 * C2];

// ---------------- helpers ----------------
__device__ __forceinline__ uint32_t s2u(const void* p) {
    uint32_t a;
    asm("{ .reg .u64 t; cvta.to.shared.u64 t, %1; cvt.u32.u64 %0, t; }" : "=r"(a) : "l"(p));
    return a;
}

#define STS128(addr, a, b, c, d) \
    asm volatile("st.shared.v4.b32 [%0], {%1, %2, %3, %4};" :: "r"(addr), "r"(a), "r"(b), "r"(c), "r"(d) : "memory")

#define LDMX4(r, addr) \
    asm volatile("ldmatrix.sync.aligned.m8n8.x4.shared.b16 {%0,%1,%2,%3}, [%4];" \
        : "=r"((r)[0]), "=r"((r)[1]), "=r"((r)[2]), "=r"((r)[3]) : "r"(addr))

#define MMA_BF16(d, a, b) \
    asm volatile("mma.sync.aligned.m16n8k16.row.col.f32.bf16.bf16.f32 " \
        "{%0,%1,%2,%3}, {%4,%5,%6,%7}, {%8,%9}, {%0,%1,%2,%3};" \
        : "+f"((d)[0]), "+f"((d)[1]), "+f"((d)[2]), "+f"((d)[3]) \
        : "r"((a)[0]), "r"((a)[1]), "r"((a)[2]), "r"((a)[3]), "r"((b)[0]), "r"((b)[1]))

__device__ __forceinline__ uint32_t pack_bf2(float lo_, float hi_) {
    __nv_bfloat162 t = __floats2bfloat162_rn(lo_, hi_);
    return *reinterpret_cast<uint32_t*>(&t);
}

// ---------------- KNN (K=3), reference-matching arithmetic ----------------
__global__ __launch_bounds__(128) void knn_kernel(
    const float* __restrict__ y_points, const float* __restrict__ x_points,
    int* __restrict__ out_idx, float* __restrict__ out_w)
{
    __shared__ float xp[NX * 3];
    __shared__ float xs[NX];
    const int m0 = blockIdx.x * 128;
    const int b  = m0 / NY;
    const float* xb = x_points + (size_t)b * NX * 3;
    for (int i = threadIdx.x; i < NX * 3; i += 128) xp[i] = xb[i];
    __syncthreads();
    for (int j = threadIdx.x; j < NX; j += 128) {
        const float x0 = xp[3 * j + 0], x1 = xp[3 * j + 1], x2 = xp[3 * j + 2];
        xs[j] = __fadd_rn(__fadd_rn(__fmul_rn(x0, x0), __fmul_rn(x1, x1)), __fmul_rn(x2, x2));
    }
    __syncthreads();

    const int m = m0 + threadIdx.x;
    const float py0 = y_points[(size_t)m * 3 + 0];
    const float py1 = y_points[(size_t)m * 3 + 1];
    const float py2 = y_points[(size_t)m * 3 + 2];
    const float yy = __fadd_rn(__fadd_rn(__fmul_rn(py0, py0), __fmul_rn(py1, py1)), __fmul_rn(py2, py2));

    float d0 = 3.4e38f, d1 = 3.4e38f, d2 = 3.4e38f;
    int   i0 = 0, i1 = 0, i2 = 0;
    for (int j = 0; j < NX; j++) {
        const float x0 = xp[3 * j + 0], x1 = xp[3 * j + 1], x2 = xp[3 * j + 2];
        const float dot = __fadd_rn(__fadd_rn(__fmul_rn(py0, x0), __fmul_rn(py1, x1)), __fmul_rn(py2, x2));
        const float d = __fsub_rn(__fadd_rn(yy, xs[j]), __fmul_rn(2.0f, dot));
        if (d < d2) {
            if (d < d1) {
                d2 = d1; i2 = i1;
                if (d < d0) { d1 = d0; i1 = i0; d0 = d; i0 = j; }
                else        { d1 = d;  i1 = j; }
            } else { d2 = d; i2 = j; }
        }
    }
    const float w0 = __fdiv_rn(1.0f, __fadd_rn(d0, 1e-8f));
    const float w1 = __fdiv_rn(1.0f, __fadd_rn(d1, 1e-8f));
    const float w2 = __fdiv_rn(1.0f, __fadd_rn(d2, 1e-8f));
    const float s  = __fadd_rn(__fadd_rn(w0, w1), w2);
    out_idx[m * 3 + 0] = i0; out_idx[m * 3 + 1] = i1; out_idx[m * 3 + 2] = i2;
    out_w[m * 3 + 0] = __fdiv_rn(w0, s);
    out_w[m * 3 + 1] = __fdiv_rn(w1, s);
    out_w[m * 3 + 2] = __fdiv_rn(w2, s);
}

// ---------------- gather + concat -> F [M, 384] ----------------
__global__ __launch_bounds__(DIM) void gather_kernel(
    const float* __restrict__ y_feats, const float* __restrict__ x_feats,
    const int* __restrict__ idx, const float* __restrict__ w,
    float* __restrict__ F)
{
    const int m = blockIdx.x;
    const int c = threadIdx.x;
    if (c < CY) {
        F[(size_t)m * DIM + c] = y_feats[(size_t)m * CY + c];
    } else {
        const int b  = m / NY;
        const int cc = c - CY;
        const float* xb = x_feats + (size_t)b * NX * CX;
        const int i0 = idx[m * 3 + 0], i1 = idx[m * 3 + 1], i2 = idx[m * 3 + 2];
        const float w0 = w[m * 3 + 0], w1 = w[m * 3 + 1], w2 = w[m * 3 + 2];
        const float f0 = __fmul_rn(w0, xb[(size_t)i0 * CX + cc]);
        const float f1 = __fmul_rn(w1, xb[(size_t)i1 * CX + cc]);
        const float f2 = __fmul_rn(w2, xb[(size_t)i2 * CX + cc]);
        F[(size_t)m * DIM + c] = __fadd_rn(__fadd_rn(f0, f1), f2);
    }
}

// ---------------- weight split fp32 -> bf16 hi/lo ----------------
__global__ void wconv_kernel(const float* __restrict__ W,
                             __nv_bfloat16* __restrict__ hi, __nv_bfloat16* __restrict__ lo, int n)
{
    const int i = blockIdx.x * 256 + threadIdx.x;
    if (i >= n) return;
    const float v = W[i];
    const __nv_bfloat16 h = __float2bfloat16(v);
    hi[i] = h;
    lo[i] = __float2bfloat16(v - __bfloat162float(h));
}

// ---------------- HMMA bf16-split GEMM + fused BN/ReLU(A) + fused stats ----------------
// C[M,N] = act(A)[M,K] * W[N,K]^T with W = Wh + Wl (bf16 split), A split on the fly.
// 2-term split: hh + hl + lh (drop ll, ~2^-16 rel). fp32 accumulate in HMMA.
// Block tile 128x128, 8 warps (2M x 4N), warp tile 64x32, k-chunk = 32 bf16, 2-stage pipe.
template<int KDIM, int NDIM, bool FUSE>
__global__ __launch_bounds__(256, 1) void hmma_gemm(
    const float* __restrict__ A,
    const __nv_bfloat16* __restrict__ Wh, const __nv_bfloat16* __restrict__ Wl,
    const float* __restrict__ sc, const float* __restrict__ sh,
    float* __restrict__ C, float* __restrict__ ps, float* __restrict__ pq)
{
    constexpr int KC      = 32;                 // bf16 per k-chunk
    constexpr int NCH     = KDIM / KC;
    constexpr int RSTRIDE = 80;                 // padded row stride (bytes), conflict-free ldmatrix
    constexpr int PIECE   = 128 * RSTRIDE;      // one split piece
    constexpr int STAGE   = 4 * PIECE;          // Ah, Al, Bh, Bl
    constexpr int SCSZ    = FUSE ? KDIM : 1;

    extern __shared__ uint8_t smraw[];
    __shared__ float sc_s[SCSZ], sh_s[SCSZ];
    __shared__ float red_s[2][128], red_q[2][128];

    const int tid  = threadIdx.x;
    const int lane = tid & 31, wid = tid >> 5;
    const int wm   = wid & 1,  wn  = wid >> 1;
    const int m0   = blockIdx.y * 128, n0 = blockIdx.x * 128;
    const uint32_t smem = s2u(smraw);

    if constexpr (FUSE) {
        for (int i = tid; i < KDIM; i += 256) { sc_s[i] = sc[i]; sh_s[i] = sh[i]; }
    }
    __syncthreads();

    // global-load roles: 2 threads per row, each 16 k-elems
    const int lr = tid >> 1;
    const int lh = tid & 1;
    const float*         Ag  = A  + (size_t)(m0 + lr) * KDIM + lh * 16;
    const __nv_bfloat16* Bgh = Wh + (size_t)(n0 + lr) * KDIM + lh * 16;
    const __nv_bfloat16* Bgl = Wl + (size_t)(n0 + lr) * KDIM + lh * 16;

    float4 stA[4];
    uint4  stBh[2], stBl[2];

    auto gload = [&](int c) {
        const float4* ap = (const float4*)(Ag + c * KC);
        stA[0] = ap[0]; stA[1] = ap[1]; stA[2] = ap[2]; stA[3] = ap[3];
        const uint4* bh = (const uint4*)(Bgh + c * KC);
        const uint4* bl = (const uint4*)(Bgl + c * KC);
        stBh[0] = bh[0]; stBh[1] = bh[1];
        stBl[0] = bl[0]; stBl[1] = bl[1];
    };

    auto sts = [&](int c, int st) {
        const uint32_t base = smem + st * STAGE;
        float v[16];
        #pragma unroll
        for (int q = 0; q < 4; q++) {
            v[q * 4 + 0] = stA[q].x; v[q * 4 + 1] = stA[q].y;
            v[q * 4 + 2] = stA[q].z; v[q * 4 + 3] = stA[q].w;
        }
        if constexpr (FUSE) {
            const int kb = c * KC + lh * 16;
            #pragma unroll
            for (int i = 0; i < 16; i++)
                v[i] = fmaxf(fmaf(v[i], sc_s[kb + i], sh_s[kb + i]), 0.0f);
        }
        uint32_t hB[8], lB[8];
        #pragma unroll
        for (int p = 0; p < 8; p++) {
            const __nv_bfloat162 hh = __floats2bfloat162_rn(v[2 * p], v[2 * p + 1]);
            const float2 hf = __bfloat1622float2(hh);
            hB[p] = *(const uint32_t*)&hh;
            lB[p] = pack_bf2(v[2 * p] - hf.x, v[2 * p + 1] - hf.y);
        }
        const uint32_t arow = base + lr * RSTRIDE + lh * 32;
        STS128(arow,              hB[0], hB[1], hB[2], hB[3]);
        STS128(arow + 16,         hB[4], hB[5], hB[6], hB[7]);
        STS128(arow + PIECE,      lB[0], lB[1], lB[2], lB[3]);
        STS128(arow + PIECE + 16, lB[4], lB[5], lB[6], lB[7]);
        const uint32_t brow = base + 2 * PIECE + lr * RSTRIDE + lh * 32;
        STS128(brow,              stBh[0].x, stBh[0].y, stBh[0].z, stBh[0].w);
        STS128(brow + 16,         stBh[1].x, stBh[1].y, stBh[1].z, stBh[1].w);
        STS128(brow + PIECE,      stBl[0].x, stBl[0].y, stBl[0].z, stBl[0].w);
        STS128(brow + PIECE + 16, stBl[1].x, stBl[1].y, stBl[1].z, stBl[1].w);
    };

    float acc[4][4][4];
    #pragma unroll
    for (int i = 0; i < 4; i++)
        #pragma unroll
        for (int j = 0; j < 4; j++)
            #pragma unroll
            for (int f = 0; f < 4; f++) acc[i][j][f] = 0.0f;

    const int l07 = lane & 7;
    const int b3  = (lane >> 3) & 1;
    const int b4  = (lane >> 4) & 1;

    auto mma_stage = [&](int st) {
        const uint32_t Ah_b = smem + st * STAGE;
        const uint32_t Al_b = Ah_b + PIECE;
        const uint32_t Bh_b = Ah_b + 2 * PIECE;
        const uint32_t Bl_b = Ah_b + 3 * PIECE;
        #pragma unroll
        for (int ks = 0; ks < 2; ks++) {
            const uint32_t aoff = (uint32_t)(wm * 64 + l07 + b3 * 8) * RSTRIDE + ks * 32 + b4 * 16;
            const uint32_t boff = (uint32_t)(wn * 32 + l07 + b4 * 8) * RSTRIDE + ks * 32 + b3 * 16;
            uint32_t bh[8], bl[8], af[16];
            LDMX4(bh,     Bh_b + boff);
            LDMX4(bh + 4, Bh_b + boff + 16 * RSTRIDE);
            LDMX4(bl,     Bl_b + boff);
            LDMX4(bl + 4, Bl_b + boff + 16 * RSTRIDE);
            #pragma unroll
            for (int mt = 0; mt < 4; mt++) LDMX4(af + mt * 4, Ah_b + aoff + mt * 16 * RSTRIDE);
            #pragma unroll
            for (int mt = 0; mt < 4; mt++)
                #pragma unroll
                for (int nt = 0; nt < 4; nt++) {
                    MMA_BF16(acc[mt][nt], af + mt * 4, bh + nt * 2);
                    MMA_BF16(acc[mt][nt], af + mt * 4, bl + nt * 2);
                }
            #pragma unroll
            for (int mt = 0; mt < 4; mt++) LDMX4(af + mt * 4, Al_b + aoff + mt * 16 * RSTRIDE);
            #pragma unroll
            for (int mt = 0; mt < 4; mt++)
                #pragma unroll
                for (int nt = 0; nt < 4; nt++)
                    MMA_BF16(acc[mt][nt], af + mt * 4, bh + nt * 2);
        }
    };

    // pipeline: prefetch next chunk into regs while HMMAs run on current stage
    gload(0);
    sts(0, 0);
    __syncthreads();
    for (int c = 0; c < NCH; c++) {
        if (c + 1 < NCH) gload(c + 1);
        mma_stage(c & 1);
        __syncthreads();
        if (c + 1 < NCH) { sts(c + 1, (c + 1) & 1); __syncthreads(); }
    }

    // ---- epilogue: store C + deterministic per-column stats partials ----
    const int g = lane >> 2, q4 = lane & 3;
    float s8[4][2], q8[4][2];
    #pragma unroll
    for (int nt = 0; nt < 4; nt++) { s8[nt][0] = s8[nt][1] = 0.0f; q8[nt][0] = q8[nt][1] = 0.0f; }

    #pragma unroll
    for (int mt = 0; mt < 4; mt++) {
        #pragma unroll
        for (int nt = 0; nt < 4; nt++) {
            const int row = m0 + wm * 64 + mt * 16 + g;
            const int col = n0 + wn * 32 + nt * 8 + q4 * 2;
            float2 v0 = make_float2(acc[mt][nt][0], acc[mt][nt][1]);
            float2 v1 = make_float2(acc[mt][nt][2], acc[mt][nt][3]);
            *(float2*)(C + (size_t)row * NDIM + col)       = v0;
            *(float2*)(C + (size_t)(row + 8) * NDIM + col) = v1;
            s8[nt][0] += v0.x + v1.x;
            s8[nt][1] += v0.y + v1.y;
            q8[nt][0] += v0.x * v0.x + v1.x * v1.x;
            q8[nt][1] += v0.y * v0.y + v1.y * v1.y;
        }
    }
    #pragma unroll
    for (int nt = 0; nt < 4; nt++)
        #pragma unroll
        for (int j = 0; j < 2; j++) {
            float s = s8[nt][j], q = q8[nt][j];
            #pragma unroll
            for (int off = 4; off < 32; off <<= 1) {
                s += __shfl_xor_sync(0xFFFFFFFFu, s, off);
                q += __shfl_xor_sync(0xFFFFFFFFu, q, off);
            }
            if (lane < 4) {
                const int cl = wn * 32 + nt * 8 + lane * 2 + j;
                red_s[wm][cl] = s;
                red_q[wm][cl] = q;
            }
        }
    __syncthreads();
    if (tid < 128) {
        ps[(size_t)(n0 + tid) * GRIDM + blockIdx.y] = red_s[0][tid] + red_s[1][tid];
        pq[(size_t)(n0 + tid) * GRIDM + blockIdx.y] = red_q[0][tid] + red_q[1][tid];
    }
}

// ---------------- BN finalize: reduce partials -> scale/shift ----------------
__global__ void finalize_kernel(
    const float* __restrict__ ps, const float* __restrict__ pq,
    const float* __restrict__ g, const float* __restrict__ be,
    float* __restrict__ sc, float* __restrict__ sh, int N)
{
    const int n = blockIdx.x * blockDim.x + threadIdx.x;
    if (n >= N) return;
    float s = 0.0f, q = 0.0f;
    for (int i = 0; i < GRIDM; i++) { s += ps[(size_t)n * GRIDM + i]; q += pq[(size_t)n * GRIDM + i]; }
    const float mean = s * (1.0f / (float)MROWS);
    const float var  = q * (1.0f / (float)MROWS) - mean * mean;
    const float rstd = rsqrtf(var + 1e-5f);
    const float scale = g[n] * rstd;
    sc[n] = scale;
    sh[n] = be[n] - mean * scale;
}

// ---------------- final BN+ReLU + transpose to [B, C3, NY] ----------------
__global__ __launch_bounds__(256) void output_kernel(
    const float* __restrict__ T3, const float* __restrict__ sc,
    const float* __restrict__ sh, float* __restrict__ out)
{
    __shared__ float tilebuf[32][33];
    const int mt = blockIdx.x * 32;
    const int ct = blockIdx.y * 32;
    const int tx = threadIdx.x;
    const int ty = threadIdx.y;
    #pragma unroll
    for (int i = ty; i < 32; i += 8) {
        const int c = ct + tx;
        const float v = T3[(size_t)(mt + i) * C3 + c];
        tilebuf[i][tx] = fmaxf(v * sc[c] + sh[c], 0.0f);
    }
    __syncthreads();
    const int m  = mt + tx;
    const int b  = m / NY;
    const int ny = m % NY;
    #pragma unroll
    for (int j = ty; j < 32; j += 8) {
        const int c = ct + j;
        out[((size_t)b * C3 + c) * NY + ny] = tilebuf[tx][j];
    }
}

// ---------------- launch ----------------
static void* sym_addr(const void* sym) { void* p = nullptr; cudaGetSymbolAddress(&p, sym); return p; }

extern "C" void kernel_launch(void* const* d_in, const int* in_sizes, int n_in,
                              void* d_out, int out_size)
{
    const float* y_points = (const float*)d_in[0];
    const float* y_feats  = (const float*)d_in[1];
    const float* x_points = (const float*)d_in[2];
    const float* x_feats  = (const float*)d_in[3];
    const float* W1 = (const float*)d_in[4];
    const float* g1 = (const float*)d_in[6];
    const float* be1= (const float*)d_in[7];
    const float* W2 = (const float*)d_in[8];
    const float* g2 = (const float*)d_in[10];
    const float* be2= (const float*)d_in[11];
    const float* W3 = (const float*)d_in[12];
    const float* g3 = (const float*)d_in[14];
    const float* be3= (const float*)d_in[15];
    float* out = (float*)d_out;
    // conv biases b1/b2/b3 cancel exactly through training-mode BN (y - mean(y)):
    // mean shift absorbs them and variance is unaffected, so they are unused.

    float* pF  = (float*)sym_addr(g_F);
    float* pT1 = (float*)sym_addr(g_T1);
    float* pT2 = (float*)sym_addr(g_T2);
    float* pT3 = (float*)sym_addr(g_T3);
    int*   pIdx= (int*)  sym_addr(g_idx);
    float* pW  = (float*)sym_addr(g_w);
    float* pPs = (float*)sym_addr(g_ps);
    float* pPq = (float*)sym_addr(g_pq);
    float* pSc1= (float*)sym_addr(g_sc1);
    float* pSh1= (float*)sym_addr(g_sh1);
    float* pSc2= (float*)sym_addr(g_sc2);
    float* pSh2= (float*)sym_addr(g_sh2);
    float* pSc3= (float*)sym_addr(g_sc3);
    float* pSh3= (float*)sym_addr(g_sh3);
    __nv_bfloat16* pW1h = (__nv_bfloat16*)sym_addr(g_W1h);
    __nv_bfloat16* pW1l = (__nv_bfloat16*)sym_addr(g_W1l);
    __nv_bfloat16* pW2h = (__nv_bfloat16*)sym_addr(g_W2h);
    __nv_bfloat16* pW2l = (__nv_bfloat16*)sym_addr(g_W2l);
    __nv_bfloat16* pW3h = (__nv_bfloat16*)sym_addr(g_W3h);
    __nv_bfloat16* pW3l = (__nv_bfloat16*)sym_addr(g_W3l);

    constexpr int SMEMSZ = 2 * 4 * 128 * 80;   // 81920 bytes: 2 stages x (Ah,Al,Bh,Bl)
    cudaFuncSetAttribute((const void*)hmma_gemm<DIM, C1, false>, cudaFuncAttributeMaxDynamicSharedMemorySize, SMEMSZ);
    cudaFuncSetAttribute((const void*)hmma_gemm<C1,  C2, true >, cudaFuncAttributeMaxDynamicSharedMemorySize, SMEMSZ);
    cudaFuncSetAttribute((const void*)hmma_gemm<C2,  C3, true >, cudaFuncAttributeMaxDynamicSharedMemorySize, SMEMSZ);

    // 1) KNN + interpolation weights
    knn_kernel<<<MROWS / 128, 128>>>(y_points, x_points, pIdx, pW);
    // 2) interpolate + concat
    gather_kernel<<<MROWS, DIM>>>(y_feats, x_feats, pIdx, pW, pF);
    // 3) weight bf16 hi/lo splits
    wconv_kernel<<<(C1 * DIM + 255) / 256, 256>>>(W1, pW1h, pW1l, C1 * DIM);
    wconv_kernel<<<(C2 * C1  + 255) / 256, 256>>>(W2, pW2h, pW2l, C2 * C1);
    wconv_kernel<<<(C3 * C2  + 255) / 256, 256>>>(W3, pW3h, pW3l, C3 * C2);
    // 4) layer 1 (HMMA, stats fused into epilogue)
    hmma_gemm<DIM, C1, false><<<dim3(C1 / 128, GRIDM), 256, SMEMSZ>>>(
        pF, pW1h, pW1l, nullptr, nullptr, pT1, pPs, pPq);
    finalize_kernel<<<1, C1>>>(pPs, pPq, g1, be1, pSc1, pSh1, C1);
    // 5) layer 2 (BN1+ReLU fused into A load)
    hmma_gemm<C1, C2, true><<<dim3(C2 / 128, GRIDM), 256, SMEMSZ>>>(
        pT1, pW2h, pW2l, pSc1, pSh1, pT2, pPs, pPq);
    finalize_kernel<<<1, C2>>>(pPs, pPq, g2, be2, pSc2, pSh2, C2);
    // 6) layer 3 (BN2+ReLU fused into A load)
    hmma_gemm<C2, C3, true><<<dim3(C3 / 128, GRIDM), 256, SMEMSZ>>>(
        pT2, pW3h, pW3l, pSc2, pSh2, pT3, pPs, pPq);
    finalize_kernel<<<1, C3>>>(pPs, pPq, g3, be3, pSc3, pSh3, C3);
    // 7) BN3+ReLU + transpose into [B, C3, NY]
    output_kernel<<<dim3(MROWS / 32, C3 / 32), dim3(32, 8)>>>(pT3, pSc3, pSh3, out);
}